// round 13
// baseline (speedup 1.0000x reference)
#include <cuda_runtime.h>
#include <cuda_bf16.h>
#include <cstdint>

#define NN   500000
#define FD   128
#define IN0  144
#define NG   2048
#define EPSV 1e-5f
#define TM   128
#define NTH  256
#define APST 73             // packed A stride (b32 units)

// ---- shared memory byte offsets (k_main) ----
#define F1HI_OFF  0         // 9*16*32*8  = 36864
#define F1LO_OFF  36864
#define F2HI_OFF  73728     // 8*16*32*8  = 32768
#define F2LO_OFF  106496
#define APHI_OFF  139264    // 128*73*4   = 37376
#define APLO_OFF  176640
#define SB_OFF    214016    // int[128]
#define SMEM_MAIN 214560

#define CG 8                // graphs per k_corr block
#define FDP 132             // transposed W stride in k_corr

typedef unsigned long long ull;

// ---------------- scratch ----------------
__device__ __align__(16) float g_z[(size_t)NN * FD];
__device__ __align__(16) float g_xsum[NG * IN0];
__device__ __align__(16) float g_cnt[NG];
__device__ __align__(16) float g_c1[NG * FD];
__device__ __align__(16) float g_c2[NG * FD];
__device__ __align__(16) float g_hsum[NG * FD];
__device__ __align__(16) float g_zsum[NG * FD];
__device__ __align__(16) int   g_start[NG + 1];
__device__ __align__(16) float g_colsum[FD];
__device__ __align__(16) float g_colsq[FD];
__device__ __align__(16) float g_scale[FD];
__device__ __align__(16) float g_shift[FD];

// packed = {lo16 = bf16(a), hi16 = bf16(b)}
__device__ __forceinline__ uint32_t packbf(float a, float b) {
    uint32_t r;
    asm("cvt.rn.bf16x2.f32 %0, %1, %2;" : "=r"(r) : "f"(b), "f"(a));
    return r;
}
// extract half (as fp32) from packed bf16x2: sel=0 -> low half, sel=1 -> high half
__device__ __forceinline__ float unpk(uint32_t w, int sel) {
    return __uint_as_float(sel ? (w & 0xffff0000u) : (w << 16));
}

#define MMA_B16(acc, a0, a1, a2, a3, b0, b1) \
    asm volatile("mma.sync.aligned.m16n8k16.row.col.f32.bf16.bf16.f32 " \
        "{%0,%1,%2,%3}, {%4,%5,%6,%7}, {%8,%9}, {%0,%1,%2,%3};" \
        : "+f"((acc)[0]), "+f"((acc)[1]), "+f"((acc)[2]), "+f"((acc)[3]) \
        : "r"(a0), "r"(a1), "r"(a2), "r"(a3), "r"(b0), "r"(b1))

// ---------------- K_ib: init accumulators + segment bounds ----------------
__global__ void k_ib(const int* __restrict__ batch) {
    int i = blockIdx.x * blockDim.x + threadIdx.x;
    if (i < NG * FD) { g_hsum[i] = 0.f; g_zsum[i] = 0.f; }
    if (i < FD) { g_colsum[i] = 0.f; g_colsq[i] = 0.f; }
    if (i < NN) {
        int b = batch[i];
        if (i == 0) {
            for (int g = 0; g <= b; g++) g_start[g] = 0;
        } else {
            int prev = batch[i - 1];
            for (int g = prev + 1; g <= b; g++) g_start[g] = i;
        }
        if (i == NN - 1) {
            for (int g = b + 1; g <= NG; g++) g_start[g] = NN;
        }
    }
}

// ---------------- K1: per-segment column sums of x0 ----------------
__global__ void k_segsum(const float* __restrict__ x, const float* __restrict__ pers0) {
    __shared__ float shx[4 * 128];
    __shared__ float shp[16 * 16];
    int g = blockIdx.x, t = threadIdx.x;
    int s = g_start[g], e = g_start[g + 1];
    const float2* x2 = (const float2*)x;
    const float2* p2 = (const float2*)pers0;
    if (t < 256) {
        int c2 = t & 63, ro = t >> 6;
        float ax = 0.f, ay = 0.f;
        int n = s + ro;
        #pragma unroll 4
        for (; n < e; n += 4) {
            float2 v = x2[(size_t)n * 64 + c2];
            ax += v.x; ay += v.y;
        }
        shx[ro * 128 + c2 * 2]     = ax;
        shx[ro * 128 + c2 * 2 + 1] = ay;
    } else {
        int u = t - 256;
        int p = u & 7, ro = u >> 3;
        float ax = 0.f, ay = 0.f;
        #pragma unroll 2
        for (int n = s + ro; n < e; n += 16) {
            float2 v = p2[(size_t)p * NN + n];
            ax += v.x; ay += v.y;
        }
        shp[ro * 16 + p * 2]     = ax;
        shp[ro * 16 + p * 2 + 1] = ay;
    }
    __syncthreads();
    if (t < 128) {
        float a = 0.f;
        #pragma unroll
        for (int r = 0; r < 4; r++) a += shx[r * 128 + t];
        g_xsum[g * IN0 + t] = a;
    } else if (t < 144) {
        int c = t - 128;
        float a = 0.f;
        #pragma unroll
        for (int j = 0; j < 16; j++) a += shp[j * 16 + c];
        g_xsum[g * IN0 + t] = a;
    }
    if (t == 0) g_cnt[g] = (float)(e - s);
}

// ---------------- K2/K4: c = gb - (sum/cnt) @ lw^T  (+ stat fold for WHICH=1) --
template <int WHICH, int K>
__global__ void k_corr(const float* __restrict__ lw, const float* __restrict__ gb) {
    extern __shared__ float dsm[];
    float* shw = dsm;                  // [K][FDP] transposed
    float* shm = shw + K * FDP;        // [CG][K]
    float* shc = shm + CG * K;         // [CG]
    const float* msum = WHICH ? g_hsum : g_xsum;
    float* cout       = WHICH ? g_c2   : g_c1;
    int t = threadIdx.x;               // 256
    int gbase = blockIdx.x * CG;
    for (int idx = t; idx < FD * K; idx += 256) {
        int j = idx / K;
        int k = idx - j * K;
        shw[k * FDP + j] = lw[idx];
    }
    for (int idx = t; idx < CG * K; idx += 256)
        shm[idx] = msum[gbase * K + idx];
    if (t < CG) shc[t] = 1.f / fmaxf(g_cnt[gbase + t], 1.f);
    __syncthreads();

    int grp = t >> 7;
    int c = t & 127;
    int g0 = grp * 4;
    float acc[4][4];
    #pragma unroll
    for (int a = 0; a < 4; a++)
        #pragma unroll
        for (int b = 0; b < 4; b++) acc[a][b] = 0.f;

    const float4* m0 = (const float4*)(shm + (g0 + 0) * K);
    const float4* m1 = (const float4*)(shm + (g0 + 1) * K);
    const float4* m2 = (const float4*)(shm + (g0 + 2) * K);
    const float4* m3 = (const float4*)(shm + (g0 + 3) * K);
    #pragma unroll 4
    for (int k4 = 0; k4 < K / 4; k4++) {
        float4 v0 = m0[k4], v1 = m1[k4], v2 = m2[k4], v3 = m3[k4];
        const float* wp = shw + (k4 * 4) * FDP + c;
        float w0 = wp[0], w1 = wp[FDP], w2 = wp[2 * FDP], w3 = wp[3 * FDP];
        acc[0][0] += v0.x * w0; acc[0][1] += v0.y * w1; acc[0][2] += v0.z * w2; acc[0][3] += v0.w * w3;
        acc[1][0] += v1.x * w0; acc[1][1] += v1.y * w1; acc[1][2] += v1.z * w2; acc[1][3] += v1.w * w3;
        acc[2][0] += v2.x * w0; acc[2][1] += v2.y * w1; acc[2][2] += v2.z * w2; acc[2][3] += v2.w * w3;
        acc[3][0] += v3.x * w0; acc[3][1] += v3.y * w1; acc[3][2] += v3.z * w2; acc[3][3] += v3.w * w3;
    }
    float gbv = gb[c];
    float s = 0.f, q = 0.f;
    #pragma unroll
    for (int a = 0; a < 4; a++) {
        int g = gbase + g0 + a;
        float cv = gbv - ((acc[a][0] + acc[a][1]) + (acc[a][2] + acc[a][3])) * shc[g0 + a];
        cout[g * FD + c] = cv;
        if (WHICH) {
            float cnt = g_cnt[g];
            float zs  = g_zsum[g * FD + c];
            s += cnt * cv;
            q += 2.f * zs * cv + cnt * cv * cv;
        }
    }
    if (WHICH) {
        atomicAdd(&g_colsum[c], s);
        atomicAdd(&g_colsq[c], q);
    }
}

// ---------------- warp GEMM: 32 rows x 64 cols, B fragments reused 2x ----------
template <int KC>
__device__ __forceinline__ void gemm_warp32(const uint32_t* __restrict__ aphi,
                                            const uint32_t* __restrict__ aplo,
                                            const ull* __restrict__ fhi,
                                            const ull* __restrict__ flo,
                                            int r0, int ntbase, int lane,
                                            float acc0[8][4], float acc1[8][4]) {
    int lr = lane >> 2, lc = lane & 3;
    const uint32_t* p0h = aphi + (r0 + lr) * APST;
    const uint32_t* p1h = p0h + 8 * APST;
    const uint32_t* p2h = p0h + 16 * APST;
    const uint32_t* p3h = p0h + 24 * APST;
    const uint32_t* p0l = aplo + (r0 + lr) * APST;
    const uint32_t* p1l = p0l + 8 * APST;
    const uint32_t* p2l = p0l + 16 * APST;
    const uint32_t* p3l = p0l + 24 * APST;
    #pragma unroll 3
    for (int kc = 0; kc < KC; kc++) {
        int pa = kc * 8 + lc;
        uint32_t s0a0h = p0h[pa], s0a1h = p1h[pa], s0a2h = p0h[pa + 4], s0a3h = p1h[pa + 4];
        uint32_t s0a0l = p0l[pa], s0a1l = p1l[pa], s0a2l = p0l[pa + 4], s0a3l = p1l[pa + 4];
        uint32_t s1a0h = p2h[pa], s1a1h = p3h[pa], s1a2h = p2h[pa + 4], s1a3h = p3h[pa + 4];
        uint32_t s1a0l = p2l[pa], s1a1l = p3l[pa], s1a2l = p2l[pa + 4], s1a3l = p3l[pa + 4];
        #pragma unroll
        for (int nt = 0; nt < 8; nt++) {
            ull bh = fhi[(kc * 16 + ntbase + nt) * 32 + lane];
            ull bl = flo[(kc * 16 + ntbase + nt) * 32 + lane];
            uint32_t b0h = (uint32_t)bh, b1h = (uint32_t)(bh >> 32);
            uint32_t b0l = (uint32_t)bl, b1l = (uint32_t)(bl >> 32);
            MMA_B16(acc0[nt], s0a0h, s0a1h, s0a2h, s0a3h, b0h, b1h);
            MMA_B16(acc0[nt], s0a0h, s0a1h, s0a2h, s0a3h, b0l, b1l);
            MMA_B16(acc0[nt], s0a0l, s0a1l, s0a2l, s0a3l, b0h, b1h);
            MMA_B16(acc1[nt], s1a0h, s1a1h, s1a2h, s1a3h, b0h, b1h);
            MMA_B16(acc1[nt], s1a0h, s1a1h, s1a2h, s1a3h, b0l, b1l);
            MMA_B16(acc1[nt], s1a0l, s1a1l, s1a2l, s1a3l, b0h, b1h);
        }
    }
}

// ---------------- K3: persistent fused main ----------------
__global__ __launch_bounds__(NTH, 1)
void k_main(const float* __restrict__ x, const int* __restrict__ batch,
            const float* __restrict__ pers0,
            const float* __restrict__ g1w, const float* __restrict__ g2w) {
    extern __shared__ char sal[];
    ull*      f1hi = (ull*)(sal + F1HI_OFF);
    ull*      f1lo = (ull*)(sal + F1LO_OFF);
    ull*      f2hi = (ull*)(sal + F2HI_OFF);
    ull*      f2lo = (ull*)(sal + F2LO_OFF);
    uint32_t* aphi = (uint32_t*)(sal + APHI_OFF);
    uint32_t* aplo = (uint32_t*)(sal + APLO_OFF);
    int*      sb   = (int*)(sal + SB_OFF);

    int t = threadIdx.x;
    int w = t >> 5, lane = t & 31;
    int r0 = (w >> 1) * 32;           // 4 row-groups of 32
    int h0 = (w & 1) * 64;            // 2 col-halves
    int ntbase = h0 >> 3;
    int lr = lane >> 2, lc = lane & 3;

    // ---- one-time: B fragments (hi/lo) in mma lane layout ----
    for (int idx = t; idx < 9 * 16 * 32; idx += NTH) {
        int kc = idx >> 9, rem = idx & 511;
        int nt = rem >> 5, l = rem & 31;
        int n = nt * 8 + (l >> 2);
        int k0 = kc * 16 + ((l & 3) << 1);
        const float* wr = g1w + n * IN0;
        float w00 = wr[k0], w01 = wr[k0 + 1], w10 = wr[k0 + 8], w11 = wr[k0 + 9];
        uint32_t u0 = packbf(w00, w01), u1 = packbf(w10, w11);
        f1hi[idx] = (ull)u0 | ((ull)u1 << 32);
        float r00 = w00 - unpk(u0, 0), r01 = w01 - unpk(u0, 1);
        float r10 = w10 - unpk(u1, 0), r11 = w11 - unpk(u1, 1);
        uint32_t v0 = packbf(r00, r01), v1 = packbf(r10, r11);
        f1lo[idx] = (ull)v0 | ((ull)v1 << 32);
    }
    for (int idx = t; idx < 8 * 16 * 32; idx += NTH) {
        int kc = idx >> 9, rem = idx & 511;
        int nt = rem >> 5, l = rem & 31;
        int n = nt * 8 + (l >> 2);
        int k0 = kc * 16 + ((l & 3) << 1);
        const float* wr = g2w + n * FD;
        float w00 = wr[k0], w01 = wr[k0 + 1], w10 = wr[k0 + 8], w11 = wr[k0 + 9];
        uint32_t u0 = packbf(w00, w01), u1 = packbf(w10, w11);
        f2hi[idx] = (ull)u0 | ((ull)u1 << 32);
        float r00 = w00 - unpk(u0, 0), r01 = w01 - unpk(u0, 1);
        float r10 = w10 - unpk(u1, 0), r11 = w11 - unpk(u1, 1);
        uint32_t v0 = packbf(r00, r01), v1 = packbf(r10, r11);
        f2lo[idx] = (ull)v0 | ((ull)v1 << 32);
    }

    int c = t & 127;                  // scan column
    int sel = c & 1;
    int pcw = c >> 1;
    float csum = 0.f, csq = 0.f;
    float acc0[8][4], acc1[8][4];
    const int NT = (NN + TM - 1) / TM;     // 3907
    const float2* pers2 = (const float2*)pers0;

    for (int tile = blockIdx.x; tile < NT; tile += gridDim.x) {
        int n0 = tile * TM;
        __syncthreads();   // (A) prev tile scans done; aphi/aplo free

        // ---- load + convert tile -> A1 packed hi/lo (unroll-limited: regs) ----
        {
            #pragma unroll 4
            for (int j = 0; j < 16; j++) {
                int idx = t + j * NTH;
                int r = idx >> 5, q = idx & 31;
                int n = n0 + r;
                float4 v = (n < NN) ? *(const float4*)(x + (size_t)n * FD + q * 4)
                                    : make_float4(0.f, 0.f, 0.f, 0.f);
                uint32_t* ph = aphi + r * APST + 2 * q;
                uint32_t* pl = aplo + r * APST + 2 * q;
                uint32_t u0 = packbf(v.x, v.y);
                uint32_t u1 = packbf(v.z, v.w);
                ph[0] = u0;
                ph[1] = u1;
                pl[0] = packbf(v.x - unpk(u0, 0), v.y - unpk(u0, 1));
                pl[1] = packbf(v.z - unpk(u1, 0), v.w - unpk(u1, 1));
            }
            #pragma unroll 2
            for (int j = 0; j < 4; j++) {
                int idx = t + j * NTH;
                int r = idx & 127, p = idx >> 7;
                int n = n0 + r;
                float2 v = (n < NN) ? pers2[(size_t)p * NN + n] : make_float2(0.f, 0.f);
                uint32_t hp = packbf(v.x, v.y);
                aphi[r * APST + 64 + p] = hp;
                aplo[r * APST + 64 + p] = packbf(v.x - unpk(hp, 0), v.y - unpk(hp, 1));
            }
            if (t < TM) {
                int n = n0 + t;
                sb[t] = (n < NN) ? batch[n] : -1;
            }
        }
        __syncthreads();   // (B) A1 + sb ready

        // ---- GEMM1 ----
        #pragma unroll
        for (int nt = 0; nt < 8; nt++)
            #pragma unroll
            for (int q = 0; q < 4; q++) { acc0[nt][q] = 0.f; acc1[nt][q] = 0.f; }
        gemm_warp32<9>(aphi, aplo, f1hi, f1lo, r0, ntbase, lane, acc0, acc1);
        __syncthreads();   // (C) all A1 reads done

        // ---- epilogue 1: h = relu(acc + c1[g]) -> packed A2 (unroll-limited) ----
        {
            int ra = r0 + lr, rb = ra + 8, rc2 = ra + 16, rd = ra + 24;
            int ga = sb[ra], gb_ = sb[rb], gc_ = sb[rc2], gd = sb[rd];
            #pragma unroll 2
            for (int nt = 0; nt < 8; nt++) {
                int ncol = h0 + nt * 8 + 2 * lc;
                int pc = ncol >> 1;
                float2 ca = (ga >= 0) ? *(const float2*)(g_c1 + ga * FD + ncol) : make_float2(0.f, 0.f);
                float2 cb = (gb_ >= 0) ? *(const float2*)(g_c1 + gb_ * FD + ncol) : make_float2(0.f, 0.f);
                float2 cc = (gc_ >= 0) ? *(const float2*)(g_c1 + gc_ * FD + ncol) : make_float2(0.f, 0.f);
                float2 cd = (gd >= 0) ? *(const float2*)(g_c1 + gd * FD + ncol) : make_float2(0.f, 0.f);
                float va0 = fmaxf(acc0[nt][0] + ca.x, 0.f), va1 = fmaxf(acc0[nt][1] + ca.y, 0.f);
                float vb0 = fmaxf(acc0[nt][2] + cb.x, 0.f), vb1 = fmaxf(acc0[nt][3] + cb.y, 0.f);
                float vc0 = fmaxf(acc1[nt][0] + cc.x, 0.f), vc1 = fmaxf(acc1[nt][1] + cc.y, 0.f);
                float vd0 = fmaxf(acc1[nt][2] + cd.x, 0.f), vd1 = fmaxf(acc1[nt][3] + cd.y, 0.f);
                uint32_t ua = packbf(va0, va1);
                uint32_t ub = packbf(vb0, vb1);
                uint32_t uc = packbf(vc0, vc1);
                uint32_t ud = packbf(vd0, vd1);
                aphi[ra * APST + pc] = ua;
                aphi[rb * APST + pc] = ub;
                aphi[rc2 * APST + pc] = uc;
                aphi[rd * APST + pc] = ud;
                aplo[ra * APST + pc] = packbf(va0 - unpk(ua, 0), va1 - unpk(ua, 1));
                aplo[rb * APST + pc] = packbf(vb0 - unpk(ub, 0), vb1 - unpk(ub, 1));
                aplo[rc2 * APST + pc] = packbf(vc0 - unpk(uc, 0), vc1 - unpk(uc, 1));
                aplo[rd * APST + pc] = packbf(vd0 - unpk(ud, 0), vd1 - unpk(ud, 1));
            }
        }
        __syncthreads();   // (D) A2 ready

        // ---- GEMM2 ----
        #pragma unroll
        for (int nt = 0; nt < 8; nt++)
            #pragma unroll
            for (int q = 0; q < 4; q++) { acc0[nt][q] = 0.f; acc1[nt][q] = 0.f; }
        gemm_warp32<8>(aphi, aplo, f2hi, f2lo, r0, ntbase, lane, acc0, acc1);

        // ---- hsum scan (reads packed h = hi+lo; overlaps other warps' GEMM2) ----
        {
            float run = 0.f;
            int gc = -1;
            int rb2 = (t >> 7) * 64;
            for (int r = rb2; r < rb2 + 64; r++) {
                int g = sb[r];
                if (g != gc) {
                    if (gc >= 0) atomicAdd(&g_hsum[gc * FD + c], run);
                    run = 0.f;
                    gc = g;
                }
                if (g >= 0)
                    run += unpk(aphi[r * APST + pcw], sel) + unpk(aplo[r * APST + pcw], sel);
            }
            if (gc >= 0) atomicAdd(&g_hsum[gc * FD + c], run);
        }
        __syncthreads();   // (E) GEMM2 + hsum reads of aphi/aplo done

        // ---- epilogue 2: z -> gmem (fp32) + packed z -> smem (unroll-limited) ----
        {
            int ra = r0 + lr, rb = ra + 8, rc2 = ra + 16, rd = ra + 24;
            #pragma unroll 2
            for (int nt = 0; nt < 8; nt++) {
                int ncol = h0 + nt * 8 + 2 * lc;
                int pc = ncol >> 1;
                float va0 = acc0[nt][0], va1 = acc0[nt][1];
                float vb0 = acc0[nt][2], vb1 = acc0[nt][3];
                float vc0 = acc1[nt][0], vc1 = acc1[nt][1];
                float vd0 = acc1[nt][2], vd1 = acc1[nt][3];
                if (n0 + ra < NN) *(float2*)(g_z + (size_t)(n0 + ra) * FD + ncol) = make_float2(va0, va1);
                if (n0 + rb < NN) *(float2*)(g_z + (size_t)(n0 + rb) * FD + ncol) = make_float2(vb0, vb1);
                if (n0 + rc2 < NN) *(float2*)(g_z + (size_t)(n0 + rc2) * FD + ncol) = make_float2(vc0, vc1);
                if (n0 + rd < NN) *(float2*)(g_z + (size_t)(n0 + rd) * FD + ncol) = make_float2(vd0, vd1);
                uint32_t ua = packbf(va0, va1);
                uint32_t ub = packbf(vb0, vb1);
                uint32_t uc = packbf(vc0, vc1);
                uint32_t ud = packbf(vd0, vd1);
                aphi[ra * APST + pc] = ua;
                aphi[rb * APST + pc] = ub;
                aphi[rc2 * APST + pc] = uc;
                aphi[rd * APST + pc] = ud;
                aplo[ra * APST + pc] = packbf(va0 - unpk(ua, 0), va1 - unpk(ua, 1));
                aplo[rb * APST + pc] = packbf(vb0 - unpk(ub, 0), vb1 - unpk(ub, 1));
                aplo[rc2 * APST + pc] = packbf(vc0 - unpk(uc, 0), vc1 - unpk(uc, 1));
                aplo[rd * APST + pc] = packbf(vd0 - unpk(ud, 0), vd1 - unpk(ud, 1));
            }
        }
        __syncthreads();   // (F) packed z ready

        // ---- zsum scan + column stats (reads packed z) ----
        {
            float run = 0.f;
            int gc = -1;
            int rb2 = (t >> 7) * 64;
            for (int r = rb2; r < rb2 + 64; r++) {
                int g = sb[r];
                if (g != gc) {
                    if (gc >= 0) atomicAdd(&g_zsum[gc * FD + c], run);
                    run = 0.f;
                    gc = g;
                }
                if (g >= 0) {
                    float v = unpk(aphi[r * APST + pcw], sel) + unpk(aplo[r * APST + pcw], sel);
                    run += v;
                    csum += v;
                    csq += v * v;
                }
            }
            if (gc >= 0) atomicAdd(&g_zsum[gc * FD + c], run);
        }
    }

    atomicAdd(&g_colsum[c], csum);
    atomicAdd(&g_colsq[c], csq);
}

__global__ void k_fin(const float* __restrict__ bng, const float* __restrict__ bnb) {
    int c = threadIdx.x;
    float mu  = g_colsum[c] / (float)NN;
    float var = g_colsq[c] / (float)NN - mu * mu;
    float inv = rsqrtf(var + EPSV);
    float sc  = bng[c] * inv;
    g_scale[c] = sc;
    g_shift[c] = bnb[c] - mu * sc;
}

__global__ void k_out(const float* __restrict__ x, const int* __restrict__ batch,
                      float* __restrict__ out) {
    int idx = blockIdx.x * blockDim.x + threadIdx.x;
    if (idx >= NN * 32) return;
    int n = idx >> 5;
    int qd = idx & 31;
    int c0 = qd << 2;
    int g = batch[n];
    float4 zvv = *(const float4*)(g_z + (size_t)n * FD + c0);
    float4 xv = *(const float4*)(x + (size_t)n * FD + c0);
    float4 cv = *(const float4*)(g_c2 + g * FD + c0);
    float4 sc = *(const float4*)(g_scale + c0);
    float4 sh = *(const float4*)(g_shift + c0);
    float4 o;
    o.x = xv.x + (zvv.x + cv.x) * sc.x + sh.x;
    o.y = xv.y + (zvv.y + cv.y) * sc.y + sh.y;
    o.z = xv.z + (zvv.z + cv.z) * sc.z + sh.z;
    o.w = xv.w + (zvv.w + cv.w) * sc.w + sh.w;
    ((float4*)out)[idx] = o;
}

// ---------------- host ----------------
extern "C" void kernel_launch(void* const* d_in, const int* in_sizes, int n_in,
                              void* d_out, int out_size) {
    const float* x     = (const float*)d_in[0];
    const int*   batch = (const int*)d_in[1];
    const float* pers0 = (const float*)d_in[2];
    const float* g1w   = (const float*)d_in[3];
    const float* g1b   = (const float*)d_in[4];
    const float* l1w   = (const float*)d_in[5];
    const float* g2w   = (const float*)d_in[6];
    const float* g2b   = (const float*)d_in[7];
    const float* l2w   = (const float*)d_in[8];
    const float* bng   = (const float*)d_in[9];
    const float* bnb   = (const float*)d_in[10];
    float* out = (float*)d_out;

    int sms = 148;
    cudaDeviceGetAttribute(&sms, cudaDevAttrMultiProcessorCount, 0);

    const int smem_corr1 = (IN0 * FDP + CG * IN0 + CG) * 4;
    const int smem_corr2 = (FD * FDP + CG * FD + CG) * 4;
    cudaFuncSetAttribute(k_main, cudaFuncAttributeMaxDynamicSharedMemorySize, SMEM_MAIN);
    cudaFuncSetAttribute(k_corr<0, IN0>, cudaFuncAttributeMaxDynamicSharedMemorySize, smem_corr1);
    cudaFuncSetAttribute(k_corr<1, FD>,  cudaFuncAttributeMaxDynamicSharedMemorySize, smem_corr2);

    k_ib<<<(NN + 255) / 256, 256>>>(batch);                        // 1
    k_segsum<<<NG, 384>>>(x, pers0);                               // 2
    k_corr<0, IN0><<<NG / CG, 256, smem_corr1>>>(l1w, g1b);        // 3
    k_main<<<sms, NTH, SMEM_MAIN>>>(x, batch, pers0, g1w, g2w);    // 4
    k_corr<1, FD><<<NG / CG, 256, smem_corr2>>>(l2w, g2b);         // 5
    k_fin<<<1, 128>>>(bng, bnb);                                   // 6
    k_out<<<(NN * 32 + 255) / 256, 256>>>(x, batch, out);          // 7
}

// round 14
// speedup vs baseline: 1.8054x; 1.8054x over previous
#include <cuda_runtime.h>
#include <cuda_bf16.h>
#include <cstdint>

#define NN   500000
#define FD   128
#define IN0  144
#define NG   2048
#define EPSV 1e-5f
#define TM   32             // rows per GROUP tile
#define NTH  256
#define SST  148            // stage stride (floats)
#define APST 73             // packed A stride (b32 units)

// ---- shared memory byte offsets ----
#define F1HI_OFF  0
#define F1LO_OFF  36864
#define F2HI_OFF  73728
#define F2LO_OFF  106496
#define APHI_OFF  139264    // + grp*9344   (32*73*4)
#define APLO_OFF  157952    // + grp*9344
#define STAGE_OFF 176640    // + grp*18944  (32*148*4)
#define SB_OFF    214528    // + grp*128
#define SMEM_MAIN 214784

#define CG 8
#define FDP 132

typedef unsigned long long ull;

// ---------------- scratch ----------------
__device__ __align__(16) float g_z[(size_t)NN * FD];
__device__ __align__(16) float g_xsum[NG * IN0];
__device__ __align__(16) float g_cnt[NG];
__device__ __align__(16) float g_c1[NG * FD];
__device__ __align__(16) float g_c2[NG * FD];
__device__ __align__(16) float g_hsum[NG * FD];
__device__ __align__(16) float g_zsum[NG * FD];
__device__ __align__(16) int   g_start[NG + 1];
__device__ __align__(16) float g_colsum[FD];
__device__ __align__(16) float g_colsq[FD];
__device__ __align__(16) float g_scale[FD];
__device__ __align__(16) float g_shift[FD];

__device__ __forceinline__ uint32_t packbf(float a, float b) {
    uint32_t r;
    asm("cvt.rn.bf16x2.f32 %0, %1, %2;" : "=r"(r) : "f"(b), "f"(a));
    return r;
}
__device__ __forceinline__ float unpk(uint32_t w, int sel) {
    return __uint_as_float(sel ? (w & 0xffff0000u) : (w << 16));
}

#define MMA_B16(acc, a0, a1, a2, a3, b0, b1) \
    asm volatile("mma.sync.aligned.m16n8k16.row.col.f32.bf16.bf16.f32 " \
        "{%0,%1,%2,%3}, {%4,%5,%6,%7}, {%8,%9}, {%0,%1,%2,%3};" \
        : "+f"((acc)[0]), "+f"((acc)[1]), "+f"((acc)[2]), "+f"((acc)[3]) \
        : "r"(a0), "r"(a1), "r"(a2), "r"(a3), "r"(b0), "r"(b1))

#define GBAR(id) asm volatile("bar.sync %0, 128;" :: "r"(id) : "memory")

// ---------------- K_ib ----------------
__global__ void k_ib(const int* __restrict__ batch) {
    int i = blockIdx.x * blockDim.x + threadIdx.x;
    if (i < NG * FD) { g_hsum[i] = 0.f; g_zsum[i] = 0.f; }
    if (i < FD) { g_colsum[i] = 0.f; g_colsq[i] = 0.f; }
    if (i < NN) {
        int b = batch[i];
        if (i == 0) {
            for (int g = 0; g <= b; g++) g_start[g] = 0;
        } else {
            int prev = batch[i - 1];
            for (int g = prev + 1; g <= b; g++) g_start[g] = i;
        }
        if (i == NN - 1) {
            for (int g = b + 1; g <= NG; g++) g_start[g] = NN;
        }
    }
}

// ---------------- K1: per-segment column sums ----------------
__global__ void k_segsum(const float* __restrict__ x, const float* __restrict__ pers0) {
    __shared__ float shx[4 * 128];
    __shared__ float shp[16 * 16];
    int g = blockIdx.x, t = threadIdx.x;
    int s = g_start[g], e = g_start[g + 1];
    const float2* x2 = (const float2*)x;
    const float2* p2 = (const float2*)pers0;
    if (t < 256) {
        int c2 = t & 63, ro = t >> 6;
        float ax = 0.f, ay = 0.f;
        int n = s + ro;
        #pragma unroll 4
        for (; n < e; n += 4) {
            float2 v = x2[(size_t)n * 64 + c2];
            ax += v.x; ay += v.y;
        }
        shx[ro * 128 + c2 * 2]     = ax;
        shx[ro * 128 + c2 * 2 + 1] = ay;
    } else {
        int u = t - 256;
        int p = u & 7, ro = u >> 3;
        float ax = 0.f, ay = 0.f;
        #pragma unroll 2
        for (int n = s + ro; n < e; n += 16) {
            float2 v = p2[(size_t)p * NN + n];
            ax += v.x; ay += v.y;
        }
        shp[ro * 16 + p * 2]     = ax;
        shp[ro * 16 + p * 2 + 1] = ay;
    }
    __syncthreads();
    if (t < 128) {
        float a = 0.f;
        #pragma unroll
        for (int r = 0; r < 4; r++) a += shx[r * 128 + t];
        g_xsum[g * IN0 + t] = a;
    } else if (t < 144) {
        int c = t - 128;
        float a = 0.f;
        #pragma unroll
        for (int j = 0; j < 16; j++) a += shp[j * 16 + c];
        g_xsum[g * IN0 + t] = a;
    }
    if (t == 0) g_cnt[g] = (float)(e - s);
}

// ---------------- K2/K4 ----------------
template <int WHICH, int K>
__global__ void k_corr(const float* __restrict__ lw, const float* __restrict__ gb) {
    extern __shared__ float dsm[];
    float* shw = dsm;
    float* shm = shw + K * FDP;
    float* shc = shm + CG * K;
    const float* msum = WHICH ? g_hsum : g_xsum;
    float* cout       = WHICH ? g_c2   : g_c1;
    int t = threadIdx.x;
    int gbase = blockIdx.x * CG;
    for (int idx = t; idx < FD * K; idx += 256) {
        int j = idx / K;
        int k = idx - j * K;
        shw[k * FDP + j] = lw[idx];
    }
    for (int idx = t; idx < CG * K; idx += 256)
        shm[idx] = msum[gbase * K + idx];
    if (t < CG) shc[t] = 1.f / fmaxf(g_cnt[gbase + t], 1.f);
    __syncthreads();

    int grp = t >> 7;
    int c = t & 127;
    int g0 = grp * 4;
    float acc[4][4];
    #pragma unroll
    for (int a = 0; a < 4; a++)
        #pragma unroll
        for (int b = 0; b < 4; b++) acc[a][b] = 0.f;

    const float4* m0 = (const float4*)(shm + (g0 + 0) * K);
    const float4* m1 = (const float4*)(shm + (g0 + 1) * K);
    const float4* m2 = (const float4*)(shm + (g0 + 2) * K);
    const float4* m3 = (const float4*)(shm + (g0 + 3) * K);
    #pragma unroll 4
    for (int k4 = 0; k4 < K / 4; k4++) {
        float4 v0 = m0[k4], v1 = m1[k4], v2 = m2[k4], v3 = m3[k4];
        const float* wp = shw + (k4 * 4) * FDP + c;
        float w0 = wp[0], w1 = wp[FDP], w2 = wp[2 * FDP], w3 = wp[3 * FDP];
        acc[0][0] += v0.x * w0; acc[0][1] += v0.y * w1; acc[0][2] += v0.z * w2; acc[0][3] += v0.w * w3;
        acc[1][0] += v1.x * w0; acc[1][1] += v1.y * w1; acc[1][2] += v1.z * w2; acc[1][3] += v1.w * w3;
        acc[2][0] += v2.x * w0; acc[2][1] += v2.y * w1; acc[2][2] += v2.z * w2; acc[2][3] += v2.w * w3;
        acc[3][0] += v3.x * w0; acc[3][1] += v3.y * w1; acc[3][2] += v3.z * w2; acc[3][3] += v3.w * w3;
    }
    float gbv = gb[c];
    float s = 0.f, q = 0.f;
    #pragma unroll
    for (int a = 0; a < 4; a++) {
        int g = gbase + g0 + a;
        float cv = gbv - ((acc[a][0] + acc[a][1]) + (acc[a][2] + acc[a][3])) * shc[g0 + a];
        cout[g * FD + c] = cv;
        if (WHICH) {
            float cnt = g_cnt[g];
            float zs  = g_zsum[g * FD + c];
            s += cnt * cv;
            q += 2.f * zs * cv + cnt * cv * cv;
        }
    }
    if (WHICH) {
        atomicAdd(&g_colsum[c], s);
        atomicAdd(&g_colsq[c], q);
    }
}

// ---------------- warp GEMM: 16 rows x 64 cols (per warp of a group) ----------
template <int KC>
__device__ __forceinline__ void gemm_warp(const uint32_t* __restrict__ aphi,
                                          const uint32_t* __restrict__ aplo,
                                          const ull* __restrict__ fhi,
                                          const ull* __restrict__ flo,
                                          int r0, int ntbase, int lane,
                                          float acc[8][4]) {
    int lr = lane >> 2, lc = lane & 3;
    const uint32_t* h0p = aphi + (r0 + lr) * APST;
    const uint32_t* h1p = h0p + 8 * APST;
    const uint32_t* l0p = aplo + (r0 + lr) * APST;
    const uint32_t* l1p = l0p + 8 * APST;
    #pragma unroll 1
    for (int kc = 0; kc < KC; kc++) {
        int pa = kc * 8 + lc;
        uint32_t a0h = h0p[pa], a1h = h1p[pa], a2h = h0p[pa + 4], a3h = h1p[pa + 4];
        uint32_t a0l = l0p[pa], a1l = l1p[pa], a2l = l0p[pa + 4], a3l = l1p[pa + 4];
        #pragma unroll
        for (int nt = 0; nt < 8; nt++) {
            ull bh = fhi[(kc * 16 + ntbase + nt) * 32 + lane];
            ull bl = flo[(kc * 16 + ntbase + nt) * 32 + lane];
            uint32_t b0h = (uint32_t)bh, b1h = (uint32_t)(bh >> 32);
            uint32_t b0l = (uint32_t)bl, b1l = (uint32_t)(bl >> 32);
            MMA_B16(acc[nt], a0h, a1h, a2h, a3h, b0h, b1h);
            MMA_B16(acc[nt], a0h, a1h, a2h, a3h, b0l, b1l);
            MMA_B16(acc[nt], a0l, a1l, a2l, a3l, b0h, b1h);
        }
    }
}

// ---------------- K3: persistent fused main, two pipelines per CTA ----------------
__global__ __launch_bounds__(NTH, 1)
void k_main(const float* __restrict__ x, const int* __restrict__ batch,
            const float* __restrict__ pers0,
            const float* __restrict__ g1w, const float* __restrict__ g2w) {
    extern __shared__ char sal[];
    ull* f1hi = (ull*)(sal + F1HI_OFF);
    ull* f1lo = (ull*)(sal + F1LO_OFF);
    ull* f2hi = (ull*)(sal + F2HI_OFF);
    ull* f2lo = (ull*)(sal + F2LO_OFF);

    int t = threadIdx.x;
    int grp = t >> 7;                 // pipeline group 0/1
    int gt = t & 127;                 // thread within group
    int w2 = gt >> 5, lane = gt & 31; // warp within group
    int r0 = (w2 >> 1) * 16;          // 2 row-groups of 16
    int h0 = (w2 & 1) * 64;           // 2 col-halves
    int ntbase = h0 >> 3;
    int lr = lane >> 2, lc = lane & 3;
    int barid = 1 + grp;

    uint32_t* aphi = (uint32_t*)(sal + APHI_OFF + grp * 9344);
    uint32_t* aplo = (uint32_t*)(sal + APLO_OFF + grp * 9344);
    float*    stage = (float*)(sal + STAGE_OFF + grp * 18944);
    int*      sb   = (int*)(sal + SB_OFF + grp * 128);

    // ---- one-time: B fragments (hi/lo) in mma lane layout (whole CTA) ----
    for (int idx = t; idx < 9 * 16 * 32; idx += NTH) {
        int kc = idx >> 9, rem = idx & 511;
        int nt = rem >> 5, l = rem & 31;
        int n = nt * 8 + (l >> 2);
        int k0 = kc * 16 + ((l & 3) << 1);
        const float* wr = g1w + n * IN0;
        float w00 = wr[k0], w01 = wr[k0 + 1], w10 = wr[k0 + 8], w11 = wr[k0 + 9];
        uint32_t u0 = packbf(w00, w01), u1 = packbf(w10, w11);
        f1hi[idx] = (ull)u0 | ((ull)u1 << 32);
        float r00 = w00 - unpk(u0, 0), r01 = w01 - unpk(u0, 1);
        float r10 = w10 - unpk(u1, 0), r11 = w11 - unpk(u1, 1);
        uint32_t v0 = packbf(r00, r01), v1 = packbf(r10, r11);
        f1lo[idx] = (ull)v0 | ((ull)v1 << 32);
    }
    for (int idx = t; idx < 8 * 16 * 32; idx += NTH) {
        int kc = idx >> 9, rem = idx & 511;
        int nt = rem >> 5, l = rem & 31;
        int n = nt * 8 + (l >> 2);
        int k0 = kc * 16 + ((l & 3) << 1);
        const float* wr = g2w + n * FD;
        float w00 = wr[k0], w01 = wr[k0 + 1], w10 = wr[k0 + 8], w11 = wr[k0 + 9];
        uint32_t u0 = packbf(w00, w01), u1 = packbf(w10, w11);
        f2hi[idx] = (ull)u0 | ((ull)u1 << 32);
        float r00 = w00 - unpk(u0, 0), r01 = w01 - unpk(u0, 1);
        float r10 = w10 - unpk(u1, 0), r11 = w11 - unpk(u1, 1);
        uint32_t v0 = packbf(r00, r01), v1 = packbf(r10, r11);
        f2lo[idx] = (ull)v0 | ((ull)v1 << 32);
    }
    __syncthreads();    // weights visible to both groups

    int c = gt;                       // scan/stat column (0..127)
    float csum = 0.f, csq = 0.f;
    float acc[8][4];
    const int NT = NN / TM;           // 15625 exactly
    const int STEP = gridDim.x * 2;
    const float2* pers2 = (const float2*)pers0;

    // ---- prefetch registers ----
    float4 nx[8];
    float2 np[2];
    int nb = -1;
    float2 c1a[8], c1b[8];

    int tile0 = blockIdx.x * 2 + grp;
    if (tile0 < NT) {
        int n0 = tile0 * TM;
        #pragma unroll
        for (int j = 0; j < 8; j++) {
            int idx = gt + j * 128;
            int r = idx >> 5, q = idx & 31;
            nx[j] = *(const float4*)(x + (size_t)(n0 + r) * FD + q * 4);
        }
        #pragma unroll
        for (int j = 0; j < 2; j++) {
            int idx = gt + j * 128;
            int r = idx & 31, p = idx >> 5;
            np[j] = pers2[(size_t)p * NN + (n0 + r)];
        }
        if (gt < TM) nb = batch[n0 + gt];
    }

    for (int tile = tile0; tile < NT; tile += STEP) {
        int n0 = tile * TM;
        GBAR(barid);   // (A) prev tile's scans done

        // ---- store prefetched tile into stage ----
        #pragma unroll
        for (int j = 0; j < 8; j++) {
            int idx = gt + j * 128;
            int r = idx >> 5, q = idx & 31;
            *(float4*)(stage + r * SST + q * 4) = nx[j];
        }
        #pragma unroll
        for (int j = 0; j < 2; j++) {
            int idx = gt + j * 128;
            int r = idx & 31, p = idx >> 5;
            *(float2*)(stage + r * SST + 128 + p * 2) = np[j];
        }
        if (gt < TM) sb[gt] = nb;
        GBAR(barid);   // (B) stage + sb ready

        // ---- prefetch c1 corrections ----
        {
            int ra = r0 + lr, rb = ra + 8;
            int ga = sb[ra], gb_ = sb[rb];
            #pragma unroll
            for (int nt = 0; nt < 8; nt++) {
                int ncol = h0 + nt * 8 + 2 * lc;
                c1a[nt] = (ga >= 0) ? *(const float2*)(g_c1 + ga * FD + ncol)
                                    : make_float2(0.f, 0.f);
                c1b[nt] = (gb_ >= 0) ? *(const float2*)(g_c1 + gb_ * FD + ncol)
                                     : make_float2(0.f, 0.f);
            }
        }

        // ---- convert rows -> packed bf16 hi/lo (A1) ----
        {
            int row = gt >> 2, part = gt & 3;
            const float2* srow2 = (const float2*)(stage + row * SST);
            #pragma unroll
            for (int j = 0; j < 18; j++) {
                int pc = part * 18 + j;
                float2 v = srow2[pc];
                uint32_t hp = packbf(v.x, v.y);
                aphi[row * APST + pc] = hp;
                aplo[row * APST + pc] = packbf(v.x - unpk(hp, 0), v.y - unpk(hp, 1));
            }
        }
        GBAR(barid);   // (B2) A1 ready

        // ---- issue next-tile prefetch (hidden behind GEMMs) ----
        {
            int tn = tile + STEP;
            if (tn < NT) {
                int m0 = tn * TM;
                #pragma unroll
                for (int j = 0; j < 8; j++) {
                    int idx = gt + j * 128;
                    int r = idx >> 5, q = idx & 31;
                    nx[j] = *(const float4*)(x + (size_t)(m0 + r) * FD + q * 4);
                }
                #pragma unroll
                for (int j = 0; j < 2; j++) {
                    int idx = gt + j * 128;
                    int r = idx & 31, p = idx >> 5;
                    np[j] = pers2[(size_t)p * NN + (m0 + r)];
                }
                if (gt < TM) nb = batch[m0 + gt];
            }
        }

        // ---- GEMM1 ----
        #pragma unroll
        for (int nt = 0; nt < 8; nt++)
            #pragma unroll
            for (int q = 0; q < 4; q++) acc[nt][q] = 0.f;
        gemm_warp<9>(aphi, aplo, f1hi, f1lo, r0, ntbase, lane, acc);
        GBAR(barid);   // (C) A1 reads done

        // ---- epilogue 1: h = relu(acc + c1) -> stage + A2 hi/lo ----
        {
            int ra = r0 + lr, rb = ra + 8;
            #pragma unroll
            for (int nt = 0; nt < 8; nt++) {
                int ncol = h0 + nt * 8 + 2 * lc;
                int pc = (ncol >> 1);
                float ha0 = fmaxf(acc[nt][0] + c1a[nt].x, 0.f);
                float ha1 = fmaxf(acc[nt][1] + c1a[nt].y, 0.f);
                float hb0 = fmaxf(acc[nt][2] + c1b[nt].x, 0.f);
                float hb1 = fmaxf(acc[nt][3] + c1b[nt].y, 0.f);
                *(float2*)(stage + ra * SST + ncol) = make_float2(ha0, ha1);
                *(float2*)(stage + rb * SST + ncol) = make_float2(hb0, hb1);
                uint32_t hpa = packbf(ha0, ha1);
                aphi[ra * APST + pc] = hpa;
                aplo[ra * APST + pc] = packbf(ha0 - unpk(hpa, 0), ha1 - unpk(hpa, 1));
                uint32_t hpb = packbf(hb0, hb1);
                aphi[rb * APST + pc] = hpb;
                aplo[rb * APST + pc] = packbf(hb0 - unpk(hpb, 0), hb1 - unpk(hpb, 1));
            }
        }
        GBAR(barid);   // (D) A2 + h-stage ready

        // ---- GEMM2 ----
        #pragma unroll
        for (int nt = 0; nt < 8; nt++)
            #pragma unroll
            for (int q = 0; q < 4; q++) acc[nt][q] = 0.f;
        gemm_warp<8>(aphi, aplo, f2hi, f2lo, r0, ntbase, lane, acc);

        // ---- hsum (run-length; overlaps in-flight MMAs) ----
        {
            float run = 0.f;
            int gc = -1;
            for (int r = 0; r < TM; r++) {
                int g = sb[r];
                if (g != gc) {
                    if (gc >= 0) atomicAdd(&g_hsum[gc * FD + c], run);
                    run = 0.f;
                    gc = g;
                }
                if (g >= 0) run += stage[r * SST + c];
            }
            if (gc >= 0) atomicAdd(&g_hsum[gc * FD + c], run);
        }
        GBAR(barid);   // (E) h-stage free

        // ---- epilogue 2: z -> stage ----
        {
            int ra = r0 + lr, rb = ra + 8;
            #pragma unroll
            for (int nt = 0; nt < 8; nt++) {
                int ncol = h0 + nt * 8 + 2 * lc;
                *(float2*)(stage + ra * SST + ncol) = make_float2(acc[nt][0], acc[nt][1]);
                *(float2*)(stage + rb * SST + ncol) = make_float2(acc[nt][2], acc[nt][3]);
            }
        }
        GBAR(barid);   // (F) z-stage ready

        // ---- zsum + coalesced z write + column stats ----
        {
            float run = 0.f;
            int gc = -1;
            for (int r = 0; r < TM; r++) {
                int g = sb[r];
                float v = stage[r * SST + c];
                if (g != gc) {
                    if (gc >= 0) atomicAdd(&g_zsum[gc * FD + c], run);
                    run = 0.f;
                    gc = g;
                }
                if (g >= 0) {
                    run += v;
                    csum += v;
                    csq += v * v;
                    g_z[(size_t)(n0 + r) * FD + c] = v;
                }
            }
            if (gc >= 0) atomicAdd(&g_zsum[gc * FD + c], run);
        }
    }

    atomicAdd(&g_colsum[c], csum);
    atomicAdd(&g_colsq[c], csq);
}

__global__ void k_fin(const float* __restrict__ bng, const float* __restrict__ bnb) {
    int c = threadIdx.x;
    float mu  = g_colsum[c] / (float)NN;
    float var = g_colsq[c] / (float)NN - mu * mu;
    float inv = rsqrtf(var + EPSV);
    float sc  = bng[c] * inv;
    g_scale[c] = sc;
    g_shift[c] = bnb[c] - mu * sc;
}

__global__ void k_out(const float* __restrict__ x, const int* __restrict__ batch,
                      float* __restrict__ out) {
    int idx = blockIdx.x * blockDim.x + threadIdx.x;
    if (idx >= NN * 32) return;
    int n = idx >> 5;
    int qd = idx & 31;
    int c0 = qd << 2;
    int g = batch[n];
    float4 zvv = *(const float4*)(g_z + (size_t)n * FD + c0);
    float4 xv = *(const float4*)(x + (size_t)n * FD + c0);
    float4 cv = *(const float4*)(g_c2 + g * FD + c0);
    float4 sc = *(const float4*)(g_scale + c0);
    float4 sh = *(const float4*)(g_shift + c0);
    float4 o;
    o.x = xv.x + (zvv.x + cv.x) * sc.x + sh.x;
    o.y = xv.y + (zvv.y + cv.y) * sc.y + sh.y;
    o.z = xv.z + (zvv.z + cv.z) * sc.z + sh.z;
    o.w = xv.w + (zvv.w + cv.w) * sc.w + sh.w;
    ((float4*)out)[idx] = o;
}

// ---------------- host ----------------
extern "C" void kernel_launch(void* const* d_in, const int* in_sizes, int n_in,
                              void* d_out, int out_size) {
    const float* x     = (const float*)d_in[0];
    const int*   batch = (const int*)d_in[1];
    const float* pers0 = (const float*)d_in[2];
    const float* g1w   = (const float*)d_in[3];
    const float* g1b   = (const float*)d_in[4];
    const float* l1w   = (const float*)d_in[5];
    const float* g2w   = (const float*)d_in[6];
    const float* g2b   = (const float*)d_in[7];
    const float* l2w   = (const float*)d_in[8];
    const float* bng   = (const float*)d_in[9];
    const float* bnb   = (const float*)d_in[10];
    float* out = (float*)d_out;

    int sms = 148;
    cudaDeviceGetAttribute(&sms, cudaDevAttrMultiProcessorCount, 0);

    const int smem_corr1 = (IN0 * FDP + CG * IN0 + CG) * 4;
    const int smem_corr2 = (FD * FDP + CG * FD + CG) * 4;
    cudaFuncSetAttribute(k_main, cudaFuncAttributeMaxDynamicSharedMemorySize, SMEM_MAIN);
    cudaFuncSetAttribute(k_corr<0, IN0>, cudaFuncAttributeMaxDynamicSharedMemorySize, smem_corr1);
    cudaFuncSetAttribute(k_corr<1, FD>,  cudaFuncAttributeMaxDynamicSharedMemorySize, smem_corr2);

    k_ib<<<(NN + 255) / 256, 256>>>(batch);                        // 1
    k_segsum<<<NG, 384>>>(x, pers0);                               // 2
    k_corr<0, IN0><<<NG / CG, 256, smem_corr1>>>(l1w, g1b);        // 3
    k_main<<<sms, NTH, SMEM_MAIN>>>(x, batch, pers0, g1w, g2w);    // 4
    k_corr<1, FD><<<NG / CG, 256, smem_corr2>>>(l2w, g2b);         // 5
    k_fin<<<1, 128>>>(bng, bnb);                                   // 6
    k_out<<<(NN * 32 + 255) / 256, 256>>>(x, batch, out);          // 7
}